// round 1
// baseline (speedup 1.0000x reference)
#include <cuda_runtime.h>

#define HID 128
#define NNODES_MAX 20000

// Scratch (allocation-free rule: __device__ globals)
__device__ float g_agg[NNODES_MAX * HID];   // 10.24 MB sum buffer
__device__ float g_cnt[NNODES_MAX];
__device__ int   g_is64;

// ---------------------------------------------------------------------------
// Kernel 1: zero scratch, assume int64 until proven otherwise
// ---------------------------------------------------------------------------
__global__ void zero_kernel(int n_nodes) {
    int idx = blockIdx.x * blockDim.x + threadIdx.x;
    int stride = gridDim.x * blockDim.x;
    int tot4 = (n_nodes * HID) / 4;
    float4* a4 = reinterpret_cast<float4*>(g_agg);
    float4 z = make_float4(0.f, 0.f, 0.f, 0.f);
    for (int i = idx; i < tot4; i += stride) a4[i] = z;
    for (int i = idx; i < n_nodes; i += stride) g_cnt[i] = 0.f;
    if (idx == 0) g_is64 = 1;
}

// ---------------------------------------------------------------------------
// Kernel 2: detect edge_index dtype. If int64 with values < 2^31, every odd
// 32-bit word (high half) is zero. If int32, odd words are real indices.
// ---------------------------------------------------------------------------
__global__ void detect_kernel(const unsigned* __restrict__ words, int n_check) {
    int bad = 0;
    for (int i = threadIdx.x; i < n_check; i += blockDim.x)
        if (words[2 * i + 1] != 0u) bad = 1;
    if (__syncthreads_or(bad)) {
        if (threadIdx.x == 0) g_is64 = 0;
    }
}

// ---------------------------------------------------------------------------
// Kernel 3: edge scatter. One warp per edge: 32 lanes x float4 = 128 floats.
// Vector reduction red.global.add.v4.f32 -> 1 RED per lane per edge.
// ---------------------------------------------------------------------------
__global__ void __launch_bounds__(256) edge_kernel(
    const void* __restrict__ ei,
    const float* __restrict__ feat,
    int E)
{
    int warp = (blockIdx.x * blockDim.x + threadIdx.x) >> 5;
    int lane = threadIdx.x & 31;
    if (warp >= E) return;

    long long src, dst;
    if (g_is64) {
        const long long* e64 = (const long long*)ei;
        src = e64[warp];
        dst = e64[E + warp];
    } else {
        const int* e32 = (const int*)ei;
        src = e32[warp];
        dst = e32[E + warp];
    }

    const float4* s = reinterpret_cast<const float4*>(feat + (size_t)src * HID);
    float4 v = s[lane];
    float* d = g_agg + (size_t)dst * HID + lane * 4;
    asm volatile("red.global.add.v4.f32 [%0], {%1,%2,%3,%4};"
                 :: "l"(d), "f"(v.x), "f"(v.y), "f"(v.z), "f"(v.w)
                 : "memory");
    if (lane == 0) atomicAdd(g_cnt + dst, 1.0f);
}

// ---------------------------------------------------------------------------
// Kernel 4: fused GEMM epilogue.
//   out[r] = (agg[r]/max(cnt[r],1)) @ Wl^T + feat[r] @ Wr^T + bl
// Treated as M=20000, K=256, N=128 GEMM with virtual A = [agg*inv | feat]
// and virtual B[k][c] = Wl[c][k] (k<128) / Wr[c][k-128].
// Block: 256 threads, 64x128 output tile, 4x8 per-thread microtile.
// ---------------------------------------------------------------------------
__global__ void __launch_bounds__(256) gemm_kernel(
    const float* __restrict__ feat,
    const float* __restrict__ Wl,
    const float* __restrict__ bl,
    const float* __restrict__ Wr,
    float* __restrict__ out,
    int n_nodes)
{
    __shared__ float sA[16][65];    // [kk][row] (padded)
    __shared__ float sB[16][132];   // [kk][col] (padded)
    __shared__ float sInv[64];

    int tid = threadIdx.x;
    int tx = tid & 15;              // 0..15 -> output cols tx + 16*j
    int ty = tid >> 4;              // 0..15 -> output rows ty*4 + i
    int row0 = blockIdx.x * 64;

    if (tid < 64) {
        int r = row0 + tid;
        float c = (r < n_nodes) ? g_cnt[r] : 1.f;
        sInv[tid] = 1.f / fmaxf(c, 1.f);
    }
    __syncthreads();

    float acc[4][8];
#pragma unroll
    for (int i = 0; i < 4; i++)
#pragma unroll
        for (int j = 0; j < 8; j++) acc[i][j] = 0.f;

    // A-tile load mapping: thread -> (row a_r, 4 consecutive k at a_k)
    int a_r = tid >> 2;             // 0..63
    int a_k = (tid & 3) * 4;        // 0,4,8,12
    // B-tile load mapping: thread -> (kk = b_kk, cols b_c0 + 16*v)
    int b_kk = tid & 15;
    int b_c0 = tid >> 4;

    for (int ck = 0; ck < 16; ck++) {
        int k0 = (ck & 7) * 16;
        bool first = (ck < 8);      // first 8 chunks: agg half; last 8: feat half

        // --- gmem loads into registers ---
        int grow = row0 + a_r;
        float4 av = make_float4(0.f, 0.f, 0.f, 0.f);
        if (grow < n_nodes) {
            if (first) {
                av = *reinterpret_cast<const float4*>(
                    g_agg + (size_t)grow * HID + k0 + a_k);
                float s = sInv[a_r];
                av.x *= s; av.y *= s; av.z *= s; av.w *= s;
            } else {
                av = *reinterpret_cast<const float4*>(
                    feat + (size_t)grow * HID + k0 + a_k);
            }
        }
        const float* W = first ? Wl : Wr;
        float bv[8];
#pragma unroll
        for (int v = 0; v < 8; v++) {
            int c = b_c0 + 16 * v;
            bv[v] = W[c * HID + k0 + b_kk];
        }

        __syncthreads();            // previous-iter smem reads done
        sA[a_k + 0][a_r] = av.x;
        sA[a_k + 1][a_r] = av.y;
        sA[a_k + 2][a_r] = av.z;
        sA[a_k + 3][a_r] = av.w;
#pragma unroll
        for (int v = 0; v < 8; v++) sB[b_kk][b_c0 + 16 * v] = bv[v];
        __syncthreads();

        // --- 16-deep K microloop ---
#pragma unroll
        for (int kk = 0; kk < 16; kk++) {
            float a_f[4], b_f[8];
#pragma unroll
            for (int i = 0; i < 4; i++) a_f[i] = sA[kk][ty * 4 + i];
#pragma unroll
            for (int j = 0; j < 8; j++) b_f[j] = sB[kk][tx + 16 * j];
#pragma unroll
            for (int i = 0; i < 4; i++)
#pragma unroll
                for (int j = 0; j < 8; j++)
                    acc[i][j] += a_f[i] * b_f[j];
        }
    }

    // --- epilogue: bias + store ---
#pragma unroll
    for (int i = 0; i < 4; i++) {
        int r = row0 + ty * 4 + i;
        if (r < n_nodes) {
#pragma unroll
            for (int j = 0; j < 8; j++) {
                int c = tx + 16 * j;
                out[(size_t)r * HID + c] = acc[i][j] + bl[c];
            }
        }
    }
}

// ---------------------------------------------------------------------------
extern "C" void kernel_launch(void* const* d_in, const int* in_sizes, int n_in,
                              void* d_out, int out_size)
{
    const float* feat = (const float*)d_in[0];
    const void*  ei   = d_in[1];
    const float* Wl   = (const float*)d_in[2];
    const float* bl   = (const float*)d_in[3];
    const float* Wr   = (const float*)d_in[4];
    float* out = (float*)d_out;

    int n_nodes = in_sizes[0] / HID;        // 20000
    int E = in_sizes[1] / 2;                // 640000 (element count same for i32/i64)

    zero_kernel<<<592, 256>>>(n_nodes);
    int n_check = E < 4096 ? E : 4096;
    detect_kernel<<<1, 256>>>((const unsigned*)ei, n_check);
    int edge_blocks = (E + 7) / 8;          // 8 warps/block, 1 warp/edge
    edge_kernel<<<edge_blocks, 256>>>(ei, feat, E);
    int gemm_blocks = (n_nodes + 63) / 64;
    gemm_kernel<<<gemm_blocks, 256>>>(feat, Wl, bl, Wr, out, n_nodes);
}

// round 2
// speedup vs baseline: 1.0103x; 1.0103x over previous
#include <cuda_runtime.h>

#define HID 128
#define NMAX 20000
#define EMAX 640000

// ---- scratch (__device__ globals; allocation-free rule) ----
__device__ int   g_is64;
__device__ int   g_cnt[NMAX];
__device__ int   g_prefix[NMAX + 1];
__device__ int   g_cursor[NMAX];
__device__ int   g_srcs[EMAX];
__device__ float g_agg[NMAX * HID];   // mean-aggregated features (pre-divided)

// ---------------------------------------------------------------------------
__global__ void zero_init(int n) {
    int i = blockIdx.x * blockDim.x + threadIdx.x;
    if (i < n) g_cnt[i] = 0;
    if (i == 0) g_is64 = 1;
}

// int64-with-small-values has all-zero high words; int32 does not.
__global__ void detect_kernel(const unsigned* __restrict__ w, int m) {
    int bad = 0;
    for (int i = threadIdx.x; i < m; i += blockDim.x)
        if (w[2 * i + 1] != 0u) bad = 1;
    if (__syncthreads_or(bad) && threadIdx.x == 0) g_is64 = 0;
}

// ---------------------------------------------------------------------------
__global__ void hist_kernel(const void* __restrict__ ei, int E) {
    int e = blockIdx.x * blockDim.x + threadIdx.x;
    if (e >= E) return;
    int dst = g_is64 ? (int)((const long long*)ei)[E + e]
                     : ((const int*)ei)[E + e];
    atomicAdd(&g_cnt[dst], 1);
}

// Single-block exclusive scan over counts -> CSR offsets (+ cursor copy).
__global__ void scan_kernel(int n) {
    __shared__ int sums[256];
    int t = threadIdx.x;
    int chunk = (n + 255) / 256;
    int beg = t * chunk;
    int end = min(beg + chunk, n);
    int s = 0;
    for (int i = beg; i < end; i++) s += g_cnt[i];
    sums[t] = s;
    __syncthreads();
    for (int off = 1; off < 256; off <<= 1) {
        int v = (t >= off) ? sums[t - off] : 0;
        __syncthreads();
        sums[t] += v;
        __syncthreads();
    }
    int run = (t == 0) ? 0 : sums[t - 1];
    for (int i = beg; i < end; i++) {
        int c = g_cnt[i];
        g_prefix[i] = run;
        g_cursor[i] = run;
        run += c;
    }
    if (t == 255) g_prefix[n] = run;
}

__global__ void scatter_kernel(const void* __restrict__ ei, int E) {
    int e = blockIdx.x * blockDim.x + threadIdx.x;
    if (e >= E) return;
    int src, dst;
    if (g_is64) {
        const long long* p = (const long long*)ei;
        src = (int)p[e];
        dst = (int)p[E + e];
    } else {
        const int* p = (const int*)ei;
        src = p[e];
        dst = p[E + e];
    }
    int pos = atomicAdd(&g_cursor[dst], 1);
    g_srcs[pos] = src;
}

// ---------------------------------------------------------------------------
// One warp per dst node: gather-sum src features (4-deep MLP), write mean.
// ---------------------------------------------------------------------------
__global__ void __launch_bounds__(256) agg_kernel(const float* __restrict__ feat,
                                                  int n) {
    int node = (blockIdx.x * blockDim.x + threadIdx.x) >> 5;
    int lane = threadIdx.x & 31;
    if (node >= n) return;
    int beg = g_prefix[node], end = g_prefix[node + 1];

    float4 a0 = make_float4(0.f, 0.f, 0.f, 0.f);
    float4 a1 = a0, a2 = a0, a3 = a0;
    int e = beg;
    for (; e + 4 <= end; e += 4) {
        int s0 = g_srcs[e + 0], s1 = g_srcs[e + 1];
        int s2 = g_srcs[e + 2], s3 = g_srcs[e + 3];
        float4 v0 = *(const float4*)(feat + (size_t)s0 * HID + lane * 4);
        float4 v1 = *(const float4*)(feat + (size_t)s1 * HID + lane * 4);
        float4 v2 = *(const float4*)(feat + (size_t)s2 * HID + lane * 4);
        float4 v3 = *(const float4*)(feat + (size_t)s3 * HID + lane * 4);
        a0.x += v0.x; a0.y += v0.y; a0.z += v0.z; a0.w += v0.w;
        a1.x += v1.x; a1.y += v1.y; a1.z += v1.z; a1.w += v1.w;
        a2.x += v2.x; a2.y += v2.y; a2.z += v2.z; a2.w += v2.w;
        a3.x += v3.x; a3.y += v3.y; a3.z += v3.z; a3.w += v3.w;
    }
    for (; e < end; e++) {
        float4 v = *(const float4*)(feat + (size_t)g_srcs[e] * HID + lane * 4);
        a0.x += v.x; a0.y += v.y; a0.z += v.z; a0.w += v.w;
    }
    float inv = (end > beg) ? 1.f / (float)(end - beg) : 0.f;
    float4 s;
    s.x = (a0.x + a1.x + a2.x + a3.x) * inv;
    s.y = (a0.y + a1.y + a2.y + a3.y) * inv;
    s.z = (a0.z + a1.z + a2.z + a3.z) * inv;
    s.w = (a0.w + a1.w + a2.w + a3.w) * inv;
    *(float4*)(g_agg + (size_t)node * HID + lane * 4) = s;
}

// ---------------------------------------------------------------------------
// Fused GEMM: out = agg @ Wl^T + feat @ Wr^T + bl
// Virtual M=20000, K=256, N=128. BM=64, BN=128, BK=16, 128 threads, 8x8 micro.
// Double-buffered smem with register staging.
// ---------------------------------------------------------------------------
__global__ void __launch_bounds__(128) gemm_kernel(
    const float* __restrict__ feat,
    const float* __restrict__ Wl,
    const float* __restrict__ bl,
    const float* __restrict__ Wr,
    float* __restrict__ out,
    int n)
{
    __shared__ float sA[2][16][64];    // [buf][kk][row]
    __shared__ float sB[2][16][128];   // [buf][kk][col]

    int tid = threadIdx.x;
    int tx = tid & 15;                 // col group: cols tx*8 .. tx*8+7
    int ty = tid >> 4;                 // row group: rows ty*8 .. ty*8+7
    int row0 = blockIdx.x * 64;

    // A-load mapping: row a_r, 8 consecutive k at k0+a_k
    int a_r = tid >> 1;                // 0..63
    int a_k = (tid & 1) * 8;           // 0 or 8

    float acc[8][8];
#pragma unroll
    for (int i = 0; i < 8; i++)
#pragma unroll
        for (int j = 0; j < 8; j++) acc[i][j] = 0.f;

    float4 ra0, ra1, rb[4];

    auto loadAB = [&](int ck) {
        int k0 = (ck & 7) * 16;
        const float* A = (ck < 8) ? g_agg : feat;
        const float* W = (ck < 8) ? Wl : Wr;
        int r = row0 + a_r;
        if (r < n) {
            ra0 = *(const float4*)(A + (size_t)r * HID + k0 + a_k);
            ra1 = *(const float4*)(A + (size_t)r * HID + k0 + a_k + 4);
        } else {
            ra0 = make_float4(0.f, 0.f, 0.f, 0.f);
            ra1 = ra0;
        }
#pragma unroll
        for (int q = 0; q < 4; q++)
            rb[q] = *(const float4*)(W + (size_t)tid * HID + k0 + q * 4);
    };

    auto storeAB = [&](int b) {
        sA[b][a_k + 0][a_r] = ra0.x; sA[b][a_k + 1][a_r] = ra0.y;
        sA[b][a_k + 2][a_r] = ra0.z; sA[b][a_k + 3][a_r] = ra0.w;
        sA[b][a_k + 4][a_r] = ra1.x; sA[b][a_k + 5][a_r] = ra1.y;
        sA[b][a_k + 6][a_r] = ra1.z; sA[b][a_k + 7][a_r] = ra1.w;
#pragma unroll
        for (int q = 0; q < 4; q++) {
            sB[b][q * 4 + 0][tid] = rb[q].x;
            sB[b][q * 4 + 1][tid] = rb[q].y;
            sB[b][q * 4 + 2][tid] = rb[q].z;
            sB[b][q * 4 + 3][tid] = rb[q].w;
        }
    };

    loadAB(0);
    storeAB(0);
    __syncthreads();

#pragma unroll 2
    for (int ck = 0; ck < 16; ck++) {
        if (ck < 15) loadAB(ck + 1);   // gmem latency hides behind compute
        int b = ck & 1;
#pragma unroll
        for (int kk = 0; kk < 16; kk++) {
            float4 af0 = *(const float4*)&sA[b][kk][ty * 8];
            float4 af1 = *(const float4*)&sA[b][kk][ty * 8 + 4];
            float4 bf0 = *(const float4*)&sB[b][kk][tx * 8];
            float4 bf1 = *(const float4*)&sB[b][kk][tx * 8 + 4];
            float av[8] = {af0.x, af0.y, af0.z, af0.w, af1.x, af1.y, af1.z, af1.w};
            float bv[8] = {bf0.x, bf0.y, bf0.z, bf0.w, bf1.x, bf1.y, bf1.z, bf1.w};
#pragma unroll
            for (int i = 0; i < 8; i++)
#pragma unroll
                for (int j = 0; j < 8; j++)
                    acc[i][j] += av[i] * bv[j];
        }
        if (ck < 15) {
            // all warps passed prev sync => done reading buf[(ck+1)&1]
            storeAB((ck + 1) & 1);
            __syncthreads();
        }
    }

    float4 bias0 = *(const float4*)(bl + tx * 8);
    float4 bias1 = *(const float4*)(bl + tx * 8 + 4);
    float bb[8] = {bias0.x, bias0.y, bias0.z, bias0.w,
                   bias1.x, bias1.y, bias1.z, bias1.w};
#pragma unroll
    for (int i = 0; i < 8; i++) {
        int r = row0 + ty * 8 + i;
        if (r < n) {
            float4 o0, o1;
            o0.x = acc[i][0] + bb[0]; o0.y = acc[i][1] + bb[1];
            o0.z = acc[i][2] + bb[2]; o0.w = acc[i][3] + bb[3];
            o1.x = acc[i][4] + bb[4]; o1.y = acc[i][5] + bb[5];
            o1.z = acc[i][6] + bb[6]; o1.w = acc[i][7] + bb[7];
            *(float4*)(out + (size_t)r * HID + tx * 8) = o0;
            *(float4*)(out + (size_t)r * HID + tx * 8 + 4) = o1;
        }
    }
}

// ---------------------------------------------------------------------------
extern "C" void kernel_launch(void* const* d_in, const int* in_sizes, int n_in,
                              void* d_out, int out_size)
{
    const float* feat = (const float*)d_in[0];
    const void*  ei   = d_in[1];
    const float* Wl   = (const float*)d_in[2];
    const float* bl   = (const float*)d_in[3];
    const float* Wr   = (const float*)d_in[4];
    float* out = (float*)d_out;

    int n = in_sizes[0] / HID;          // 20000
    int E = in_sizes[1] / 2;            // 640000

    zero_init<<<(n + 255) / 256, 256>>>(n);
    int n_check = E < 4096 ? E : 4096;
    detect_kernel<<<1, 256>>>((const unsigned*)ei, n_check);

    int eb = (E + 255) / 256;
    hist_kernel<<<eb, 256>>>(ei, E);
    scan_kernel<<<1, 256>>>(n);
    scatter_kernel<<<eb, 256>>>(ei, E);

    int ab = (n * 32 + 255) / 256;      // one warp per node
    agg_kernel<<<ab, 256>>>(feat, n);

    gemm_kernel<<<(n + 63) / 64, 128>>>(feat, Wl, bl, Wr, out, n);
}

// round 3
// speedup vs baseline: 1.0466x; 1.0359x over previous
#include <cuda_runtime.h>

#define HID 128
#define NMAX 20000
#define EMAX 640000

// ---- scratch (__device__ globals; allocation-free rule) ----
__device__ int   g_is64;
__device__ int   g_cnt[NMAX];
__device__ int   g_prefix[NMAX + 1];
__device__ int   g_cursor[NMAX];
__device__ int   g_srcs[EMAX];
__device__ float g_agg[NMAX * HID];   // mean-aggregated features (pre-divided)

// ---------------------------------------------------------------------------
// Kernel 1: zero counters; block 0 additionally probes edge_index dtype.
// int64-with-small-values has all-zero high 32-bit words; int32 does not.
// ---------------------------------------------------------------------------
__global__ void init_kernel(const unsigned* __restrict__ w, int m, int n) {
    int i = blockIdx.x * blockDim.x + threadIdx.x;
    if (i < n) g_cnt[i] = 0;
    if (i == 0) g_is64 = 1;
    if (blockIdx.x == 0) {
        int bad = 0;
        for (int j = threadIdx.x; j < m; j += blockDim.x)
            if (w[2 * j + 1] != 0u) bad = 1;
        if (__syncthreads_or(bad) && threadIdx.x == 0) g_is64 = 0;
    }
}

// ---------------------------------------------------------------------------
__global__ void hist_kernel(const void* __restrict__ ei, int E) {
    int e = blockIdx.x * blockDim.x + threadIdx.x;
    if (e >= E) return;
    int dst = g_is64 ? (int)((const long long*)ei)[E + e]
                     : ((const int*)ei)[E + e];
    atomicAdd(&g_cnt[dst], 1);
}

// ---------------------------------------------------------------------------
// Single-block exclusive scan, 1024 threads, warp-shuffle two-level scan.
// ---------------------------------------------------------------------------
__global__ void __launch_bounds__(1024) scan_kernel(int n) {
    __shared__ int warp_sums[32];
    int t = threadIdx.x;
    int lane = t & 31, wid = t >> 5;
    int chunk = (n + 1023) / 1024;            // 20 for n=20000
    int beg = t * chunk;
    int end = min(beg + chunk, n);

    int s = 0;
    for (int i = beg; i < end; i++) s += g_cnt[i];

    // warp inclusive scan
    int v = s;
#pragma unroll
    for (int o = 1; o < 32; o <<= 1) {
        int u = __shfl_up_sync(0xffffffffu, v, o);
        if (lane >= o) v += u;
    }
    if (lane == 31) warp_sums[wid] = v;
    __syncthreads();
    if (wid == 0) {
        int w = warp_sums[lane];
#pragma unroll
        for (int o = 1; o < 32; o <<= 1) {
            int u = __shfl_up_sync(0xffffffffu, w, o);
            if (lane >= o) w += u;
        }
        warp_sums[lane] = w;
    }
    __syncthreads();

    int run = v - s + (wid > 0 ? warp_sums[wid - 1] : 0);  // exclusive prefix
    for (int i = beg; i < end; i++) {
        int c = g_cnt[i];
        g_prefix[i] = run;
        g_cursor[i] = run;
        run += c;
    }
    if (t == 0) g_prefix[n] = warp_sums[31];   // total
}

__global__ void scatter_kernel(const void* __restrict__ ei, int E) {
    int e = blockIdx.x * blockDim.x + threadIdx.x;
    if (e >= E) return;
    int src, dst;
    if (g_is64) {
        const long long* p = (const long long*)ei;
        src = (int)p[e];
        dst = (int)p[E + e];
    } else {
        const int* p = (const int*)ei;
        src = p[e];
        dst = p[E + e];
    }
    int pos = atomicAdd(&g_cursor[dst], 1);
    g_srcs[pos] = src;
}

// ---------------------------------------------------------------------------
// One warp per dst node: gather-sum src features (4-deep MLP), write mean.
// ---------------------------------------------------------------------------
__global__ void __launch_bounds__(256) agg_kernel(const float* __restrict__ feat,
                                                  int n) {
    int node = (blockIdx.x * blockDim.x + threadIdx.x) >> 5;
    int lane = threadIdx.x & 31;
    if (node >= n) return;
    int beg = g_prefix[node], end = g_prefix[node + 1];

    float4 a0 = make_float4(0.f, 0.f, 0.f, 0.f);
    float4 a1 = a0, a2 = a0, a3 = a0;
    int e = beg;
    for (; e + 4 <= end; e += 4) {
        int s0 = g_srcs[e + 0], s1 = g_srcs[e + 1];
        int s2 = g_srcs[e + 2], s3 = g_srcs[e + 3];
        float4 v0 = *(const float4*)(feat + (size_t)s0 * HID + lane * 4);
        float4 v1 = *(const float4*)(feat + (size_t)s1 * HID + lane * 4);
        float4 v2 = *(const float4*)(feat + (size_t)s2 * HID + lane * 4);
        float4 v3 = *(const float4*)(feat + (size_t)s3 * HID + lane * 4);
        a0.x += v0.x; a0.y += v0.y; a0.z += v0.z; a0.w += v0.w;
        a1.x += v1.x; a1.y += v1.y; a1.z += v1.z; a1.w += v1.w;
        a2.x += v2.x; a2.y += v2.y; a2.z += v2.z; a2.w += v2.w;
        a3.x += v3.x; a3.y += v3.y; a3.z += v3.z; a3.w += v3.w;
    }
    for (; e < end; e++) {
        float4 v = *(const float4*)(feat + (size_t)g_srcs[e] * HID + lane * 4);
        a0.x += v.x; a0.y += v.y; a0.z += v.z; a0.w += v.w;
    }
    float inv = (end > beg) ? 1.f / (float)(end - beg) : 0.f;
    float4 s;
    s.x = (a0.x + a1.x + a2.x + a3.x) * inv;
    s.y = (a0.y + a1.y + a2.y + a3.y) * inv;
    s.z = (a0.z + a1.z + a2.z + a3.z) * inv;
    s.w = (a0.w + a1.w + a2.w + a3.w) * inv;
    *(float4*)(g_agg + (size_t)node * HID + lane * 4) = s;
}

// ---------------------------------------------------------------------------
// Fused GEMM: out = agg @ Wl^T + feat @ Wr^T + bl
// Virtual M=20000, K=256, N=128. BM=64, BN=128, BK=16, 128 threads, 8x8 micro.
// Double-buffered smem with register staging.
// ---------------------------------------------------------------------------
__global__ void __launch_bounds__(128) gemm_kernel(
    const float* __restrict__ feat,
    const float* __restrict__ Wl,
    const float* __restrict__ bl,
    const float* __restrict__ Wr,
    float* __restrict__ out,
    int n)
{
    __shared__ float sA[2][16][64];    // [buf][kk][row]
    __shared__ float sB[2][16][128];   // [buf][kk][col]

    int tid = threadIdx.x;
    int tx = tid & 15;                 // col group: cols tx*8 .. tx*8+7
    int ty = tid >> 4;                 // row group: rows ty*8 .. ty*8+7
    int row0 = blockIdx.x * 64;

    int a_r = tid >> 1;                // 0..63
    int a_k = (tid & 1) * 8;           // 0 or 8

    float acc[8][8];
#pragma unroll
    for (int i = 0; i < 8; i++)
#pragma unroll
        for (int j = 0; j < 8; j++) acc[i][j] = 0.f;

    float4 ra0, ra1, rb[4];

    auto loadAB = [&](int ck) {
        int k0 = (ck & 7) * 16;
        const float* A = (ck < 8) ? g_agg : feat;
        const float* W = (ck < 8) ? Wl : Wr;
        int r = row0 + a_r;
        if (r < n) {
            ra0 = *(const float4*)(A + (size_t)r * HID + k0 + a_k);
            ra1 = *(const float4*)(A + (size_t)r * HID + k0 + a_k + 4);
        } else {
            ra0 = make_float4(0.f, 0.f, 0.f, 0.f);
            ra1 = ra0;
        }
#pragma unroll
        for (int q = 0; q < 4; q++)
            rb[q] = *(const float4*)(W + (size_t)tid * HID + k0 + q * 4);
    };

    auto storeAB = [&](int b) {
        sA[b][a_k + 0][a_r] = ra0.x; sA[b][a_k + 1][a_r] = ra0.y;
        sA[b][a_k + 2][a_r] = ra0.z; sA[b][a_k + 3][a_r] = ra0.w;
        sA[b][a_k + 4][a_r] = ra1.x; sA[b][a_k + 5][a_r] = ra1.y;
        sA[b][a_k + 6][a_r] = ra1.z; sA[b][a_k + 7][a_r] = ra1.w;
#pragma unroll
        for (int q = 0; q < 4; q++) {
            sB[b][q * 4 + 0][tid] = rb[q].x;
            sB[b][q * 4 + 1][tid] = rb[q].y;
            sB[b][q * 4 + 2][tid] = rb[q].z;
            sB[b][q * 4 + 3][tid] = rb[q].w;
        }
    };

    loadAB(0);
    storeAB(0);
    __syncthreads();

#pragma unroll 2
    for (int ck = 0; ck < 16; ck++) {
        if (ck < 15) loadAB(ck + 1);
        int b = ck & 1;
#pragma unroll
        for (int kk = 0; kk < 16; kk++) {
            float4 af0 = *(const float4*)&sA[b][kk][ty * 8];
            float4 af1 = *(const float4*)&sA[b][kk][ty * 8 + 4];
            float4 bf0 = *(const float4*)&sB[b][kk][tx * 8];
            float4 bf1 = *(const float4*)&sB[b][kk][tx * 8 + 4];
            float av[8] = {af0.x, af0.y, af0.z, af0.w, af1.x, af1.y, af1.z, af1.w};
            float bv[8] = {bf0.x, bf0.y, bf0.z, bf0.w, bf1.x, bf1.y, bf1.z, bf1.w};
#pragma unroll
            for (int i = 0; i < 8; i++)
#pragma unroll
                for (int j = 0; j < 8; j++)
                    acc[i][j] += av[i] * bv[j];
        }
        if (ck < 15) {
            storeAB((ck + 1) & 1);
            __syncthreads();
        }
    }

    float4 bias0 = *(const float4*)(bl + tx * 8);
    float4 bias1 = *(const float4*)(bl + tx * 8 + 4);
    float bb[8] = {bias0.x, bias0.y, bias0.z, bias0.w,
                   bias1.x, bias1.y, bias1.z, bias1.w};
#pragma unroll
    for (int i = 0; i < 8; i++) {
        int r = row0 + ty * 8 + i;
        if (r < n) {
            float4 o0, o1;
            o0.x = acc[i][0] + bb[0]; o0.y = acc[i][1] + bb[1];
            o0.z = acc[i][2] + bb[2]; o0.w = acc[i][3] + bb[3];
            o1.x = acc[i][4] + bb[4]; o1.y = acc[i][5] + bb[5];
            o1.z = acc[i][6] + bb[6]; o1.w = acc[i][7] + bb[7];
            *(float4*)(out + (size_t)r * HID + tx * 8) = o0;
            *(float4*)(out + (size_t)r * HID + tx * 8 + 4) = o1;
        }
    }
}

// ---------------------------------------------------------------------------
extern "C" void kernel_launch(void* const* d_in, const int* in_sizes, int n_in,
                              void* d_out, int out_size)
{
    const float* feat = (const float*)d_in[0];
    const void*  ei   = d_in[1];
    const float* Wl   = (const float*)d_in[2];
    const float* bl   = (const float*)d_in[3];
    const float* Wr   = (const float*)d_in[4];
    float* out = (float*)d_out;

    int n = in_sizes[0] / HID;          // 20000
    int E = in_sizes[1] / 2;            // 640000

    int n_check = E < 4096 ? E : 4096;
    init_kernel<<<(n + 255) / 256, 256>>>((const unsigned*)ei, n_check, n);

    int eb = (E + 255) / 256;
    hist_kernel<<<eb, 256>>>(ei, E);
    scan_kernel<<<1, 1024>>>(n);
    scatter_kernel<<<eb, 256>>>(ei, E);

    int ab = (n * 32 + 255) / 256;      // one warp per node
    agg_kernel<<<ab, 256>>>(feat, n);

    gemm_kernel<<<(n + 63) / 64, 128>>>(feat, Wl, bl, Wr, out, n);
}

// round 4
// speedup vs baseline: 1.3283x; 1.2691x over previous
#include <cuda_runtime.h>

#define HID 128
#define NMAX 20000
#define EMAX 640000

// ---- scratch (__device__ globals; allocation-free rule) ----
__device__ int   g_is64;
__device__ int   g_cnt[NMAX];
__device__ int   g_prefix[NMAX + 1];
__device__ int   g_cursor[NMAX];
__device__ int   g_srcs[EMAX];
__device__ float g_agg[NMAX * HID];   // mean-aggregated features (pre-divided)

// ---------------------------------------------------------------------------
__global__ void init_kernel(const unsigned* __restrict__ w, int m, int n) {
    int i = blockIdx.x * blockDim.x + threadIdx.x;
    if (i < n) g_cnt[i] = 0;
    if (i == 0) g_is64 = 1;
    if (blockIdx.x == 0) {
        int bad = 0;
        for (int j = threadIdx.x; j < m; j += blockDim.x)
            if (w[2 * j + 1] != 0u) bad = 1;
        if (__syncthreads_or(bad) && threadIdx.x == 0) g_is64 = 0;
    }
}

// ---------------------------------------------------------------------------
// Histogram: 4 edges/thread for atomic MLP.
// ---------------------------------------------------------------------------
__global__ void __launch_bounds__(256) hist_kernel(const void* __restrict__ ei, int E) {
    int base = (blockIdx.x * blockDim.x + threadIdx.x) * 4;
    if (base >= E) return;
    int m = min(4, E - base);
    int d[4];
    if (g_is64) {
        const long long* p = (const long long*)ei + E;
#pragma unroll
        for (int i = 0; i < 4; i++) if (i < m) d[i] = (int)p[base + i];
    } else {
        const int* p = (const int*)ei + E;
#pragma unroll
        for (int i = 0; i < 4; i++) if (i < m) d[i] = p[base + i];
    }
#pragma unroll
    for (int i = 0; i < 4; i++) if (i < m) atomicAdd(&g_cnt[d[i]], 1);
}

// ---------------------------------------------------------------------------
// Single-block exclusive scan, 1024 threads, warp-shuffle two-level scan.
// ---------------------------------------------------------------------------
__global__ void __launch_bounds__(1024) scan_kernel(int n) {
    __shared__ int warp_sums[32];
    int t = threadIdx.x;
    int lane = t & 31, wid = t >> 5;
    int chunk = (n + 1023) / 1024;
    int beg = t * chunk;
    int end = min(beg + chunk, n);

    int s = 0;
    for (int i = beg; i < end; i++) s += g_cnt[i];

    int v = s;
#pragma unroll
    for (int o = 1; o < 32; o <<= 1) {
        int u = __shfl_up_sync(0xffffffffu, v, o);
        if (lane >= o) v += u;
    }
    if (lane == 31) warp_sums[wid] = v;
    __syncthreads();
    if (wid == 0) {
        int w = warp_sums[lane];
#pragma unroll
        for (int o = 1; o < 32; o <<= 1) {
            int u = __shfl_up_sync(0xffffffffu, w, o);
            if (lane >= o) w += u;
        }
        warp_sums[lane] = w;
    }
    __syncthreads();

    int run = v - s + (wid > 0 ? warp_sums[wid - 1] : 0);
    for (int i = beg; i < end; i++) {
        int c = g_cnt[i];
        g_prefix[i] = run;
        g_cursor[i] = run;
        run += c;
    }
    if (t == 0) g_prefix[n] = warp_sums[31];
}

// ---------------------------------------------------------------------------
// Scatter: 4 edges/thread -> 4 independent atomic chains (MLP=4).
// ---------------------------------------------------------------------------
__global__ void __launch_bounds__(256) scatter_kernel(const void* __restrict__ ei, int E) {
    int base = (blockIdx.x * blockDim.x + threadIdx.x) * 4;
    if (base >= E) return;
    int m = min(4, E - base);
    int s[4], d[4];
    if (g_is64) {
        const long long* p = (const long long*)ei;
#pragma unroll
        for (int i = 0; i < 4; i++) if (i < m) { s[i] = (int)p[base + i]; d[i] = (int)p[E + base + i]; }
    } else {
        const int* p = (const int*)ei;
#pragma unroll
        for (int i = 0; i < 4; i++) if (i < m) { s[i] = p[base + i]; d[i] = p[E + base + i]; }
    }
    int pos[4];
#pragma unroll
    for (int i = 0; i < 4; i++) if (i < m) pos[i] = atomicAdd(&g_cursor[d[i]], 1);
#pragma unroll
    for (int i = 0; i < 4; i++) if (i < m) g_srcs[pos[i]] = s[i];
}

// ---------------------------------------------------------------------------
// One warp per dst node: gather-sum src features (4-deep MLP), write mean.
// ---------------------------------------------------------------------------
__global__ void __launch_bounds__(256) agg_kernel(const float* __restrict__ feat,
                                                  int n) {
    int node = (blockIdx.x * blockDim.x + threadIdx.x) >> 5;
    int lane = threadIdx.x & 31;
    if (node >= n) return;
    int beg = g_prefix[node], end = g_prefix[node + 1];

    float4 a0 = make_float4(0.f, 0.f, 0.f, 0.f);
    float4 a1 = a0, a2 = a0, a3 = a0;
    int e = beg;
    for (; e + 4 <= end; e += 4) {
        int s0 = g_srcs[e + 0], s1 = g_srcs[e + 1];
        int s2 = g_srcs[e + 2], s3 = g_srcs[e + 3];
        float4 v0 = *(const float4*)(feat + (size_t)s0 * HID + lane * 4);
        float4 v1 = *(const float4*)(feat + (size_t)s1 * HID + lane * 4);
        float4 v2 = *(const float4*)(feat + (size_t)s2 * HID + lane * 4);
        float4 v3 = *(const float4*)(feat + (size_t)s3 * HID + lane * 4);
        a0.x += v0.x; a0.y += v0.y; a0.z += v0.z; a0.w += v0.w;
        a1.x += v1.x; a1.y += v1.y; a1.z += v1.z; a1.w += v1.w;
        a2.x += v2.x; a2.y += v2.y; a2.z += v2.z; a2.w += v2.w;
        a3.x += v3.x; a3.y += v3.y; a3.z += v3.z; a3.w += v3.w;
    }
    for (; e < end; e++) {
        float4 v = *(const float4*)(feat + (size_t)g_srcs[e] * HID + lane * 4);
        a0.x += v.x; a0.y += v.y; a0.z += v.z; a0.w += v.w;
    }
    float inv = (end > beg) ? 1.f / (float)(end - beg) : 0.f;
    float4 s;
    s.x = (a0.x + a1.x + a2.x + a3.x) * inv;
    s.y = (a0.y + a1.y + a2.y + a3.y) * inv;
    s.z = (a0.z + a1.z + a2.z + a3.z) * inv;
    s.w = (a0.w + a1.w + a2.w + a3.w) * inv;
    *(float4*)(g_agg + (size_t)node * HID + lane * 4) = s;
}

// ---------------------------------------------------------------------------
// TF32 tensor-core GEMM:
//   out = agg @ Wl^T + feat @ Wr^T + bl
// Virtual M=20000, K=256, N=128. BM=128, BN=128(all), BK=16, 256 thr (8 warps
// in 2x4), warp tile 64x32, mma.m16n8k8.tf32, double-buffered swizzled smem.
// ---------------------------------------------------------------------------
#define BM 128
#define BK 16
// conflict-free swizzle: rows*16 floats; XOR col nibble-group by (row>>1)&3
#define SW(r, c) ((r) * BK + ((c) ^ ((((r) >> 1) & 3) << 2)))

__device__ __forceinline__ unsigned f2tf32(float x) {
    unsigned r;
    asm("cvt.rna.tf32.f32 %0, %1;" : "=r"(r) : "f"(x));
    return r;
}

__device__ __forceinline__ void mma_tf32(float* c, const unsigned* a, const unsigned* b) {
    asm volatile(
        "mma.sync.aligned.m16n8k8.row.col.f32.tf32.tf32.f32 "
        "{%0,%1,%2,%3},{%4,%5,%6,%7},{%8,%9},{%0,%1,%2,%3};"
        : "+f"(c[0]), "+f"(c[1]), "+f"(c[2]), "+f"(c[3])
        : "r"(a[0]), "r"(a[1]), "r"(a[2]), "r"(a[3]), "r"(b[0]), "r"(b[1]));
}

__global__ void __launch_bounds__(256) gemm_tc(
    const float* __restrict__ feat,
    const float* __restrict__ Wl,
    const float* __restrict__ bl,
    const float* __restrict__ Wr,
    float* __restrict__ out,
    int n)
{
    __shared__ unsigned sA[2][BM * BK];
    __shared__ unsigned sB[2][128 * BK];

    int tid = threadIdx.x;
    int wid = tid >> 5, lane = tid & 31;
    int wm = wid & 1;        // 0..1 : 64-row groups
    int wn = wid >> 1;       // 0..3 : 32-col groups
    int g = lane >> 2;       // group id 0..7
    int tg = lane & 3;       // thread-in-group
    int row0 = blockIdx.x * BM;

    float acc[4][4][4];
#pragma unroll
    for (int mt = 0; mt < 4; mt++)
#pragma unroll
        for (int nt = 0; nt < 4; nt++)
#pragma unroll
            for (int q = 0; q < 4; q++) acc[mt][nt][q] = 0.f;

    uint4 rga[2], rgb[2];

    // chunk ck in [0,16): ck<8 -> (agg, Wl) k0=ck*16 ; else (feat, Wr)
    auto ldg_chunk = [&](int ck) {
        const float* A = (ck < 8) ? g_agg : feat;
        const float* W = (ck < 8) ? Wl : Wr;
        int k0 = (ck & 7) * BK;
#pragma unroll
        for (int q = 0; q < 2; q++) {
            int idx = q * 256 + tid;
            int r = idx >> 2;            // 0..127
            int c4 = (idx & 3) * 4;      // 0,4,8,12
            int gr = row0 + r;
            float4 v = make_float4(0.f, 0.f, 0.f, 0.f);
            if (gr < n) v = *(const float4*)(A + (size_t)gr * HID + k0 + c4);
            rga[q] = make_uint4(f2tf32(v.x), f2tf32(v.y), f2tf32(v.z), f2tf32(v.w));
            float4 w = *(const float4*)(W + (size_t)r * HID + k0 + c4);
            rgb[q] = make_uint4(f2tf32(w.x), f2tf32(w.y), f2tf32(w.z), f2tf32(w.w));
        }
    };

    auto sts_chunk = [&](int b) {
#pragma unroll
        for (int q = 0; q < 2; q++) {
            int idx = q * 256 + tid;
            int r = idx >> 2;
            int c4 = (idx & 3) * 4;
            *(uint4*)&sA[b][SW(r, c4)] = rga[q];
            *(uint4*)&sB[b][SW(r, c4)] = rgb[q];
        }
    };

    ldg_chunk(0);
    sts_chunk(0);
    __syncthreads();

    for (int ck = 0; ck < 16; ck++) {
        if (ck < 15) ldg_chunk(ck + 1);
        int b = ck & 1;
#pragma unroll
        for (int kk = 0; kk < 2; kk++) {
            int ko = kk * 8;
            unsigned af[4][4], bf[4][2];
#pragma unroll
            for (int mt = 0; mt < 4; mt++) {
                int rb_ = wm * 64 + mt * 16;
                af[mt][0] = sA[b][SW(rb_ + g,     ko + tg)];
                af[mt][1] = sA[b][SW(rb_ + g + 8, ko + tg)];
                af[mt][2] = sA[b][SW(rb_ + g,     ko + tg + 4)];
                af[mt][3] = sA[b][SW(rb_ + g + 8, ko + tg + 4)];
            }
#pragma unroll
            for (int nt = 0; nt < 4; nt++) {
                int cb = wn * 32 + nt * 8;
                bf[nt][0] = sB[b][SW(cb + g, ko + tg)];
                bf[nt][1] = sB[b][SW(cb + g, ko + tg + 4)];
            }
#pragma unroll
            for (int mt = 0; mt < 4; mt++)
#pragma unroll
                for (int nt = 0; nt < 4; nt++)
                    mma_tf32(acc[mt][nt], af[mt], bf[nt]);
        }
        if (ck < 15) {
            sts_chunk((ck + 1) & 1);
            __syncthreads();
        }
    }

    // epilogue: bias + store (c frag: rows g, g+8; cols tg*2, tg*2+1)
#pragma unroll
    for (int nt = 0; nt < 4; nt++) {
        int c = wn * 32 + nt * 8 + tg * 2;
        float b0 = bl[c], b1 = bl[c + 1];
#pragma unroll
        for (int mt = 0; mt < 4; mt++) {
            int r = row0 + wm * 64 + mt * 16 + g;
            if (r < n) {
                float2 o = make_float2(acc[mt][nt][0] + b0, acc[mt][nt][1] + b1);
                *(float2*)(out + (size_t)r * HID + c) = o;
            }
            if (r + 8 < n) {
                float2 o = make_float2(acc[mt][nt][2] + b0, acc[mt][nt][3] + b1);
                *(float2*)(out + (size_t)(r + 8) * HID + c) = o;
            }
        }
    }
}

// ---------------------------------------------------------------------------
extern "C" void kernel_launch(void* const* d_in, const int* in_sizes, int n_in,
                              void* d_out, int out_size)
{
    const float* feat = (const float*)d_in[0];
    const void*  ei   = d_in[1];
    const float* Wl   = (const float*)d_in[2];
    const float* bl   = (const float*)d_in[3];
    const float* Wr   = (const float*)d_in[4];
    float* out = (float*)d_out;

    int n = in_sizes[0] / HID;          // 20000
    int E = in_sizes[1] / 2;            // 640000

    int n_check = E < 4096 ? E : 4096;
    init_kernel<<<(n + 255) / 256, 256>>>((const unsigned*)ei, n_check, n);

    int eb4 = (E / 4 + 255) / 256;
    hist_kernel<<<eb4, 256>>>(ei, E);
    scan_kernel<<<1, 1024>>>(n);
    scatter_kernel<<<eb4, 256>>>(ei, E);

    int ab = (n * 32 + 255) / 256;      // one warp per node
    agg_kernel<<<ab, 256>>>(feat, n);

    gemm_tc<<<(n + BM - 1) / BM, 256>>>(feat, Wl, bl, Wr, out, n);
}

// round 5
// speedup vs baseline: 1.4156x; 1.0658x over previous
#include <cuda_runtime.h>
#include <cuda_fp16.h>

#define HID 128
#define NMAX 20000
#define EMAX 640000

// ---- scratch (__device__ globals; allocation-free rule) ----
__device__ int    g_is64;
__device__ int    g_cnt[NMAX];
__device__ int    g_prefix[NMAX + 1];
__device__ int    g_cursor[NMAX];
__device__ int    g_srcs[EMAX];
__device__ __half g_feat16[NMAX * HID];   // fp16 copy of features (gather input)
__device__ float  g_agg[NMAX * HID];      // mean-aggregated features

// ---------------------------------------------------------------------------
// Kernel 1: zero counters, probe edge dtype, convert feat -> fp16.
// ---------------------------------------------------------------------------
__global__ void __launch_bounds__(256) init_kernel(
    const unsigned* __restrict__ w, int m,
    const float* __restrict__ feat, int n)
{
    int i = blockIdx.x * blockDim.x + threadIdx.x;
    int stride = gridDim.x * blockDim.x;
    if (i < n) g_cnt[i] = 0;
    if (i == 0) g_is64 = 1;
    if (blockIdx.x == 0) {
        int bad = 0;
        for (int j = threadIdx.x; j < m; j += blockDim.x)
            if (w[2 * j + 1] != 0u) bad = 1;
        if (__syncthreads_or(bad) && threadIdx.x == 0) g_is64 = 0;
    }
    // fp16 conversion: 4 floats -> 2 half2 per iteration
    int tot4 = n * HID / 4;
    const float4* f4 = (const float4*)feat;
    uint2* h4 = (uint2*)g_feat16;
    for (int k = i; k < tot4; k += stride) {
        float4 v = f4[k];
        __half2 h0 = __floats2half2_rn(v.x, v.y);
        __half2 h1 = __floats2half2_rn(v.z, v.w);
        uint2 o;
        o.x = *(unsigned*)&h0;
        o.y = *(unsigned*)&h1;
        h4[k] = o;
    }
}

// ---------------------------------------------------------------------------
// Histogram: 4 edges/thread (no return dependency -> REDG, throughput-bound).
// ---------------------------------------------------------------------------
__global__ void __launch_bounds__(256) hist_kernel(const void* __restrict__ ei, int E) {
    int base = (blockIdx.x * blockDim.x + threadIdx.x) * 4;
    if (base >= E) return;
    int m = min(4, E - base);
    int d[4];
    if (g_is64) {
        const long long* p = (const long long*)ei + E;
#pragma unroll
        for (int i = 0; i < 4; i++) if (i < m) d[i] = (int)p[base + i];
    } else {
        const int* p = (const int*)ei + E;
#pragma unroll
        for (int i = 0; i < 4; i++) if (i < m) d[i] = p[base + i];
    }
#pragma unroll
    for (int i = 0; i < 4; i++) if (i < m) atomicAdd(&g_cnt[d[i]], 1);
}

// ---------------------------------------------------------------------------
// Single-block exclusive scan, 1024 threads, warp-shuffle two-level.
// ---------------------------------------------------------------------------
__global__ void __launch_bounds__(1024) scan_kernel(int n) {
    __shared__ int warp_sums[32];
    int t = threadIdx.x;
    int lane = t & 31, wid = t >> 5;
    int chunk = (n + 1023) / 1024;
    int beg = t * chunk;
    int end = min(beg + chunk, n);

    int s = 0;
    for (int i = beg; i < end; i++) s += g_cnt[i];

    int v = s;
#pragma unroll
    for (int o = 1; o < 32; o <<= 1) {
        int u = __shfl_up_sync(0xffffffffu, v, o);
        if (lane >= o) v += u;
    }
    if (lane == 31) warp_sums[wid] = v;
    __syncthreads();
    if (wid == 0) {
        int w = warp_sums[lane];
#pragma unroll
        for (int o = 1; o < 32; o <<= 1) {
            int u = __shfl_up_sync(0xffffffffu, w, o);
            if (lane >= o) w += u;
        }
        warp_sums[lane] = w;
    }
    __syncthreads();

    int run = v - s + (wid > 0 ? warp_sums[wid - 1] : 0);
    for (int i = beg; i < end; i++) {
        int c = g_cnt[i];
        g_prefix[i] = run;
        g_cursor[i] = run;
        run += c;
    }
    if (t == 0) g_prefix[n] = warp_sums[31];
}

// ---------------------------------------------------------------------------
// Scatter: 2 edges/thread (MLP=2 while keeping SMs full of warps).
// ---------------------------------------------------------------------------
__global__ void __launch_bounds__(256) scatter_kernel(const void* __restrict__ ei, int E) {
    int base = (blockIdx.x * blockDim.x + threadIdx.x) * 2;
    if (base >= E) return;
    int m = min(2, E - base);
    int s[2], d[2];
    if (g_is64) {
        const long long* p = (const long long*)ei;
#pragma unroll
        for (int i = 0; i < 2; i++) if (i < m) { s[i] = (int)p[base + i]; d[i] = (int)p[E + base + i]; }
    } else {
        const int* p = (const int*)ei;
#pragma unroll
        for (int i = 0; i < 2; i++) if (i < m) { s[i] = p[base + i]; d[i] = p[E + base + i]; }
    }
    int pos[2];
#pragma unroll
    for (int i = 0; i < 2; i++) if (i < m) pos[i] = atomicAdd(&g_cursor[d[i]], 1);
#pragma unroll
    for (int i = 0; i < 2; i++) if (i < m) g_srcs[pos[i]] = s[i];
}

// ---------------------------------------------------------------------------
// One warp per dst node: gather-sum fp16 src features (4-deep MLP),
// fp32 accumulate, write fp32 mean.
// ---------------------------------------------------------------------------
__global__ void __launch_bounds__(256) agg_kernel(int n) {
    int node = (blockIdx.x * blockDim.x + threadIdx.x) >> 5;
    int lane = threadIdx.x & 31;
    if (node >= n) return;
    int beg = g_prefix[node], end = g_prefix[node + 1];

    const uint2* f16 = (const uint2*)g_feat16;   // 8B = 4 halves per lane

    float4 a0 = make_float4(0.f, 0.f, 0.f, 0.f);
    float4 a1 = a0, a2 = a0, a3 = a0;

    auto addv = [](float4& a, uint2 v) {
        __half2 h0 = *(__half2*)&v.x;
        __half2 h1 = *(__half2*)&v.y;
        float2 f0 = __half22float2(h0);
        float2 f1 = __half22float2(h1);
        a.x += f0.x; a.y += f0.y; a.z += f1.x; a.w += f1.y;
    };

    int e = beg;
    for (; e + 4 <= end; e += 4) {
        int s0 = g_srcs[e + 0], s1 = g_srcs[e + 1];
        int s2 = g_srcs[e + 2], s3 = g_srcs[e + 3];
        uint2 v0 = f16[(size_t)s0 * 32 + lane];
        uint2 v1 = f16[(size_t)s1 * 32 + lane];
        uint2 v2 = f16[(size_t)s2 * 32 + lane];
        uint2 v3 = f16[(size_t)s3 * 32 + lane];
        addv(a0, v0); addv(a1, v1); addv(a2, v2); addv(a3, v3);
    }
    for (; e < end; e++) {
        uint2 v = f16[(size_t)g_srcs[e] * 32 + lane];
        addv(a0, v);
    }
    float inv = (end > beg) ? 1.f / (float)(end - beg) : 0.f;
    float4 s;
    s.x = (a0.x + a1.x + a2.x + a3.x) * inv;
    s.y = (a0.y + a1.y + a2.y + a3.y) * inv;
    s.z = (a0.z + a1.z + a2.z + a3.z) * inv;
    s.w = (a0.w + a1.w + a2.w + a3.w) * inv;
    *(float4*)(g_agg + (size_t)node * HID + lane * 4) = s;
}

// ---------------------------------------------------------------------------
// TF32 tensor-core GEMM: out = agg @ Wl^T + feat @ Wr^T + bl
// BM=128, BK=16, 256 thr (2x4 warps), warp tile 64x32, m16n8k8.tf32,
// double-buffered swizzled smem.
// ---------------------------------------------------------------------------
#define BM 128
#define BK 16
#define SW(r, c) ((r) * BK + ((c) ^ ((((r) >> 1) & 3) << 2)))

__device__ __forceinline__ unsigned f2tf32(float x) {
    unsigned r;
    asm("cvt.rna.tf32.f32 %0, %1;" : "=r"(r) : "f"(x));
    return r;
}

__device__ __forceinline__ void mma_tf32(float* c, const unsigned* a, const unsigned* b) {
    asm volatile(
        "mma.sync.aligned.m16n8k8.row.col.f32.tf32.tf32.f32 "
        "{%0,%1,%2,%3},{%4,%5,%6,%7},{%8,%9},{%0,%1,%2,%3};"
        : "+f"(c[0]), "+f"(c[1]), "+f"(c[2]), "+f"(c[3])
        : "r"(a[0]), "r"(a[1]), "r"(a[2]), "r"(a[3]), "r"(b[0]), "r"(b[1]));
}

__global__ void __launch_bounds__(256) gemm_tc(
    const float* __restrict__ feat,
    const float* __restrict__ Wl,
    const float* __restrict__ bl,
    const float* __restrict__ Wr,
    float* __restrict__ out,
    int n)
{
    __shared__ unsigned sA[2][BM * BK];
    __shared__ unsigned sB[2][128 * BK];

    int tid = threadIdx.x;
    int wid = tid >> 5, lane = tid & 31;
    int wm = wid & 1;
    int wn = wid >> 1;
    int g = lane >> 2;
    int tg = lane & 3;
    int row0 = blockIdx.x * BM;

    float acc[4][4][4];
#pragma unroll
    for (int mt = 0; mt < 4; mt++)
#pragma unroll
        for (int nt = 0; nt < 4; nt++)
#pragma unroll
            for (int q = 0; q < 4; q++) acc[mt][nt][q] = 0.f;

    uint4 rga[2], rgb[2];

    auto ldg_chunk = [&](int ck) {
        const float* A = (ck < 8) ? g_agg : feat;
        const float* W = (ck < 8) ? Wl : Wr;
        int k0 = (ck & 7) * BK;
#pragma unroll
        for (int q = 0; q < 2; q++) {
            int idx = q * 256 + tid;
            int r = idx >> 2;
            int c4 = (idx & 3) * 4;
            int gr = row0 + r;
            float4 v = make_float4(0.f, 0.f, 0.f, 0.f);
            if (gr < n) v = *(const float4*)(A + (size_t)gr * HID + k0 + c4);
            rga[q] = make_uint4(f2tf32(v.x), f2tf32(v.y), f2tf32(v.z), f2tf32(v.w));
            float4 w = *(const float4*)(W + (size_t)r * HID + k0 + c4);
            rgb[q] = make_uint4(f2tf32(w.x), f2tf32(w.y), f2tf32(w.z), f2tf32(w.w));
        }
    };

    auto sts_chunk = [&](int b) {
#pragma unroll
        for (int q = 0; q < 2; q++) {
            int idx = q * 256 + tid;
            int r = idx >> 2;
            int c4 = (idx & 3) * 4;
            *(uint4*)&sA[b][SW(r, c4)] = rga[q];
            *(uint4*)&sB[b][SW(r, c4)] = rgb[q];
        }
    };

    ldg_chunk(0);
    sts_chunk(0);
    __syncthreads();

    for (int ck = 0; ck < 16; ck++) {
        if (ck < 15) ldg_chunk(ck + 1);
        int b = ck & 1;
#pragma unroll
        for (int kk = 0; kk < 2; kk++) {
            int ko = kk * 8;
            unsigned af[4][4], bf[4][2];
#pragma unroll
            for (int mt = 0; mt < 4; mt++) {
                int rb_ = wm * 64 + mt * 16;
                af[mt][0] = sA[b][SW(rb_ + g,     ko + tg)];
                af[mt][1] = sA[b][SW(rb_ + g + 8, ko + tg)];
                af[mt][2] = sA[b][SW(rb_ + g,     ko + tg + 4)];
                af[mt][3] = sA[b][SW(rb_ + g + 8, ko + tg + 4)];
            }
#pragma unroll
            for (int nt = 0; nt < 4; nt++) {
                int cb = wn * 32 + nt * 8;
                bf[nt][0] = sB[b][SW(cb + g, ko + tg)];
                bf[nt][1] = sB[b][SW(cb + g, ko + tg + 4)];
            }
#pragma unroll
            for (int mt = 0; mt < 4; mt++)
#pragma unroll
                for (int nt = 0; nt < 4; nt++)
                    mma_tf32(acc[mt][nt], af[mt], bf[nt]);
        }
        if (ck < 15) {
            sts_chunk((ck + 1) & 1);
            __syncthreads();
        }
    }

#pragma unroll
    for (int nt = 0; nt < 4; nt++) {
        int c = wn * 32 + nt * 8 + tg * 2;
        float b0 = bl[c], b1 = bl[c + 1];
#pragma unroll
        for (int mt = 0; mt < 4; mt++) {
            int r = row0 + wm * 64 + mt * 16 + g;
            if (r < n) {
                float2 o = make_float2(acc[mt][nt][0] + b0, acc[mt][nt][1] + b1);
                *(float2*)(out + (size_t)r * HID + c) = o;
            }
            if (r + 8 < n) {
                float2 o = make_float2(acc[mt][nt][2] + b0, acc[mt][nt][3] + b1);
                *(float2*)(out + (size_t)(r + 8) * HID + c) = o;
            }
        }
    }
}

// ---------------------------------------------------------------------------
extern "C" void kernel_launch(void* const* d_in, const int* in_sizes, int n_in,
                              void* d_out, int out_size)
{
    const float* feat = (const float*)d_in[0];
    const void*  ei   = d_in[1];
    const float* Wl   = (const float*)d_in[2];
    const float* bl   = (const float*)d_in[3];
    const float* Wr   = (const float*)d_in[4];
    float* out = (float*)d_out;

    int n = in_sizes[0] / HID;          // 20000
    int E = in_sizes[1] / 2;            // 640000

    int n_check = E < 4096 ? E : 4096;
    init_kernel<<<1184, 256>>>((const unsigned*)ei, n_check, feat, n);

    hist_kernel<<<(E / 4 + 255) / 256, 256>>>(ei, E);
    scan_kernel<<<1, 1024>>>(n);
    scatter_kernel<<<(E / 2 + 255) / 256, 256>>>(ei, E);

    agg_kernel<<<(n * 32 + 255) / 256, 256>>>(n);

    gemm_tc<<<(n + BM - 1) / BM, 256>>>(feat, Wl, bl, Wr, out, n);
}